// round 7
// baseline (speedup 1.0000x reference)
#include <cuda_runtime.h>
#include <cuda_bf16.h>
#include <stdint.h>

// Problem constants (fixed by the dataset)
#define LAYERS 2
#define NTRAIN 100000
#define DIM 512
#define BATCH 256
#define KNN 75
#define NCLS 10
#define NCALI 750

// ---------------- device scratch (no allocations allowed) ----------------
__device__ float g_scores[(size_t)LAYERS * BATCH * NTRAIN];  // 204.8 MB
__device__ float g_invn[LAYERS * NTRAIN];
__device__ int   g_counts[BATCH * NCLS];

// order-preserving map: float -> uint (ascending)
__device__ __forceinline__ unsigned fmap(float f) {
    unsigned u = __float_as_uint(f);
    return (u & 0x80000000u) ? ~u : (u | 0x80000000u);
}

__device__ __forceinline__ unsigned f2tf32(float x) {
    unsigned r;
    asm("cvt.rna.tf32.f32 %0, %1;" : "=r"(r) : "f"(x));
    return r;
}

__device__ __forceinline__ void mma_tf32(float d[4], const unsigned a[4], const unsigned b[2]) {
    asm volatile(
        "mma.sync.aligned.m16n8k8.row.col.f32.tf32.tf32.f32 "
        "{%0,%1,%2,%3}, {%4,%5,%6,%7}, {%8,%9}, {%0,%1,%2,%3};"
        : "+f"(d[0]), "+f"(d[1]), "+f"(d[2]), "+f"(d[3])
        : "r"(a[0]), "r"(a[1]), "r"(a[2]), "r"(a[3]), "r"(b[0]), "r"(b[1]));
}

// ---------------- kernel 1: train row inv-norms + zero counts ----------------
__global__ void norm_kernel(const float* __restrict__ train) {
    if (blockIdx.x == 0) {
        for (int i = threadIdx.x; i < BATCH * NCLS; i += blockDim.x)
            g_counts[i] = 0;
    }
    int row = blockIdx.x * 8 + (threadIdx.x >> 5);
    int lane = threadIdx.x & 31;
    if (row >= LAYERS * NTRAIN) return;
    const float4* p = (const float4*)(train + (size_t)row * DIM);
    float s = 0.f;
#pragma unroll
    for (int j = 0; j < 4; ++j) {
        float4 v = p[lane + 32 * j];
        s += v.x * v.x + v.y * v.y + v.z * v.z + v.w * v.w;
    }
#pragma unroll
    for (int o = 16; o > 0; o >>= 1) s += __shfl_down_sync(0xffffffffu, s, o);
    if (lane == 0) g_invn[row] = 1.0f / sqrtf(s);
}

// ---------------- kernel 2: scores GEMM via 3xTF32 tensor-core mma ----------------
// scores[l][b][n] = dot(q[l][b], t[l][n]) * invn[l][n]
// Block tile 128x128, GBK=8, 8 warps (2 m x 4 n), warp tile 64x32.
#define GBM 128
#define GBN 128
#define GBK 8
#define APITCH 132   // float2 pitch: conflict-free STS

__global__ void __launch_bounds__(256, 1) gemm_kernel(const float* __restrict__ qf,
                                                      const float* __restrict__ tf) {
    int l = blockIdx.z;
    const float* q = qf + (size_t)l * BATCH * DIM;
    const float* t = tf + (size_t)l * NTRAIN * DIM;
    const float* invn = g_invn + l * NTRAIN;
    float* out = g_scores + (size_t)l * BATCH * NTRAIN;

    int n0 = blockIdx.x * GBN;
    int b0 = blockIdx.y * GBM;

    // smem tiles hold (hi, lo) tf32 pairs per element, layout [k][row]
    __shared__ float2 As2[2][GBK][APITCH];
    __shared__ float2 Bs2[2][GBK][APITCH];

    int tid = threadIdx.x;
    int warp = tid >> 5;
    int lane = tid & 31;
    int g = lane >> 2;      // group id 0..7
    int r = lane & 3;       // thread-in-group 0..3
    int warpM = (warp >> 2) * 64;   // 0 or 64
    int warpN = (warp & 3) * 32;    // 0,32,64,96

    // global tile loader mapping: row lr, k offset lc (4 floats)
    int lr = tid >> 1;
    int lc = (tid & 1) * 4;
    const float* aptr = q + (size_t)(b0 + lr) * DIM + lc;
    int brow = n0 + lr;
    bool bvalid = brow < NTRAIN;
    const float* bptr = t + (size_t)brow * DIM + lc;

    float acc[4][4][4];
#pragma unroll
    for (int i = 0; i < 4; ++i)
#pragma unroll
        for (int j = 0; j < 4; ++j)
#pragma unroll
            for (int c = 0; c < 4; ++c) acc[i][j][c] = 0.f;

    // ---- prologue: tile 0 ----
    {
        float4 av = *(const float4*)aptr;
        float4 bv = bvalid ? *(const float4*)bptr : make_float4(0.f, 0.f, 0.f, 0.f);
        float aa[4] = {av.x, av.y, av.z, av.w};
        float bb[4] = {bv.x, bv.y, bv.z, bv.w};
#pragma unroll
        for (int j = 0; j < 4; ++j) {
            unsigned h = f2tf32(aa[j]);
            float hf = __uint_as_float(h);
            unsigned lo = f2tf32(aa[j] - hf);
            As2[0][lc + j][lr] = make_float2(hf, __uint_as_float(lo));
            unsigned hb = f2tf32(bb[j]);
            float hbf = __uint_as_float(hb);
            unsigned lob = f2tf32(bb[j] - hbf);
            Bs2[0][lc + j][lr] = make_float2(hbf, __uint_as_float(lob));
        }
    }
    __syncthreads();

    const int NIT = DIM / GBK;  // 64
    for (int it = 0; it < NIT; ++it) {
        int buf = it & 1;
        float4 av2, bv2;
        if (it + 1 < NIT) {
            av2 = *(const float4*)(aptr + (it + 1) * GBK);
            bv2 = bvalid ? *(const float4*)(bptr + (it + 1) * GBK)
                         : make_float4(0.f, 0.f, 0.f, 0.f);
        }

        // ---- load fragments from smem ----
        unsigned a_hi[4][4], a_lo[4][4];
        unsigned b_hi[4][2], b_lo[4][2];
#pragma unroll
        for (int i = 0; i < 4; ++i) {
            int mb = warpM + 16 * i;
            float2 t0 = As2[buf][r][mb + g];
            float2 t1 = As2[buf][r][mb + g + 8];
            float2 t2 = As2[buf][r + 4][mb + g];
            float2 t3 = As2[buf][r + 4][mb + g + 8];
            a_hi[i][0] = __float_as_uint(t0.x); a_lo[i][0] = __float_as_uint(t0.y);
            a_hi[i][1] = __float_as_uint(t1.x); a_lo[i][1] = __float_as_uint(t1.y);
            a_hi[i][2] = __float_as_uint(t2.x); a_lo[i][2] = __float_as_uint(t2.y);
            a_hi[i][3] = __float_as_uint(t3.x); a_lo[i][3] = __float_as_uint(t3.y);
        }
#pragma unroll
        for (int j = 0; j < 4; ++j) {
            int nb = warpN + 8 * j;
            float2 u0 = Bs2[buf][r][nb + g];
            float2 u1 = Bs2[buf][r + 4][nb + g];
            b_hi[j][0] = __float_as_uint(u0.x); b_lo[j][0] = __float_as_uint(u0.y);
            b_hi[j][1] = __float_as_uint(u1.x); b_lo[j][1] = __float_as_uint(u1.y);
        }

        // ---- 3xTF32 mma passes ----
#pragma unroll
        for (int i = 0; i < 4; ++i)
#pragma unroll
            for (int j = 0; j < 4; ++j) {
                mma_tf32(acc[i][j], a_hi[i], b_lo[j]);
                mma_tf32(acc[i][j], a_lo[i], b_hi[j]);
                mma_tf32(acc[i][j], a_hi[i], b_hi[j]);
            }

        // ---- stage next tile ----
        if (it + 1 < NIT) {
            int nb = buf ^ 1;
            float aa[4] = {av2.x, av2.y, av2.z, av2.w};
            float bb[4] = {bv2.x, bv2.y, bv2.z, bv2.w};
#pragma unroll
            for (int j = 0; j < 4; ++j) {
                unsigned h = f2tf32(aa[j]);
                float hf = __uint_as_float(h);
                unsigned lo = f2tf32(aa[j] - hf);
                As2[nb][lc + j][lr] = make_float2(hf, __uint_as_float(lo));
                unsigned hb = f2tf32(bb[j]);
                float hbf = __uint_as_float(hb);
                unsigned lob = f2tf32(bb[j] - hbf);
                Bs2[nb][lc + j][lr] = make_float2(hbf, __uint_as_float(lob));
            }
            __syncthreads();
        }
    }

    // ---- epilogue: scale by invn[n], float2 stores ----
#pragma unroll
    for (int j = 0; j < 4; ++j) {
        int col = n0 + warpN + 8 * j + 2 * r;
        if (col >= NTRAIN) continue;               // NTRAIN even -> col+1 also ok
        float2 iv = *(const float2*)&invn[col];
#pragma unroll
        for (int i = 0; i < 4; ++i) {
            int row0 = b0 + warpM + 16 * i + g;
            int row1 = row0 + 8;
            float2 v0, v1;
            v0.x = acc[i][j][0] * iv.x;
            v0.y = acc[i][j][1] * iv.y;
            v1.x = acc[i][j][2] * iv.x;
            v1.y = acc[i][j][3] * iv.y;
            *(float2*)&out[(size_t)row0 * NTRAIN + col] = v0;
            *(float2*)&out[(size_t)row1 * NTRAIN + col] = v1;
        }
    }
}

// ---------------- kernel 3: per-(l,b) top-75: 12-bit radix narrow + candidate pass ----------------
#define TKCAP 2048

__global__ void __launch_bounds__(256) topk_kernel(const int* __restrict__ labels) {
    int row = blockIdx.x;               // 0..511 = l*BATCH + b
    int b = row & (BATCH - 1);
    const float4* s4 = (const float4*)(g_scores + (size_t)row * NTRAIN);
    const int N4 = NTRAIN / 4;
    int tid = threadIdx.x;
    const int BS = 256;

    __shared__ unsigned hist[4096];
    __shared__ unsigned coarse[256];
    __shared__ unsigned sh_prefix;
    __shared__ int sh_kneed;
    __shared__ int sh_shift;
    __shared__ int sh_done;

    unsigned prefix = 0;
    unsigned mask = 0;
    int kneed = KNN;
    int shift = 20;

    for (int level = 0; level < 4; ++level) {
        for (int i = tid; i < 4096; i += BS) hist[i] = 0;
        __syncthreads();
        for (int i = tid; i < N4; i += BS) {
            float4 v = s4[i];
            float vv[4] = {v.x, v.y, v.z, v.w};
#pragma unroll
            for (int c = 0; c < 4; ++c) {
                unsigned u = fmap(vv[c]);
                if ((u & mask) == prefix)
                    atomicAdd(&hist[(u >> shift) & 4095], 1u);
            }
        }
        __syncthreads();
        unsigned csum = 0;
#pragma unroll
        for (int j = 0; j < 16; ++j) csum += hist[tid * 16 + j];
        coarse[tid] = csum;
        __syncthreads();
        if (tid == 0) {
            int cum = 0;
            int bsel = 0;
            unsigned bcnt = 0;
            for (int ci = 255; ci >= 0; --ci) {
                int c = (int)coarse[ci];
                if (cum + c >= kneed) {
                    for (int bi = ci * 16 + 15; bi >= ci * 16; --bi) {
                        int h = (int)hist[bi];
                        if (cum + h >= kneed) { bsel = bi; bcnt = (unsigned)h; break; }
                        cum += h;
                    }
                    break;
                }
                cum += c;
            }
            sh_prefix = prefix | ((unsigned)bsel << shift);
            sh_kneed = kneed - cum;
            sh_done = (bcnt <= TKCAP) ? 1 : 0;
            sh_shift = shift;
        }
        __syncthreads();
        prefix = sh_prefix;
        kneed = sh_kneed;
        int done = sh_done;
        __syncthreads();
        mask |= (0xFFFu << shift);
        if (done || shift == 0) break;
        shift = (shift >= 12) ? shift - 12 : 0;
    }

    unsigned T_lo = prefix;
    unsigned long long T_hi = (unsigned long long)prefix + (1ull << shift);

    __shared__ int cls[NCLS];
    __shared__ unsigned cand_u[TKCAP];
    __shared__ int cand_i[TKCAP];
    __shared__ int n_eq;
    if (tid < NCLS) cls[tid] = 0;
    if (tid == 0) n_eq = 0;
    __syncthreads();

    for (int i = tid; i < N4; i += BS) {
        float4 v = s4[i];
        float vv[4] = {v.x, v.y, v.z, v.w};
#pragma unroll
        for (int c = 0; c < 4; ++c) {
            unsigned u = fmap(vv[c]);
            if ((unsigned long long)u >= T_hi) {
                atomicAdd(&cls[labels[4 * i + c]], 1);
            } else if (u >= T_lo) {
                int p = atomicAdd(&n_eq, 1);
                if (p < TKCAP) { cand_u[p] = u; cand_i[p] = 4 * i + c; }
            }
        }
    }
    __syncthreads();

    int m = n_eq;
    if (m <= TKCAP) {
        for (int i = tid; i < m; i += BS) {
            unsigned ui = cand_u[i];
            int ii = cand_i[i];
            int rank = 0;
            for (int j = 0; j < m; ++j) {
                unsigned uj = cand_u[j];
                int ij = cand_i[j];
                rank += (uj > ui) || (uj == ui && ij < ii);
            }
            if (rank < kneed) atomicAdd(&cls[labels[ii]], 1);
        }
    } else if (tid == 0) {
        const float* s = g_scores + (size_t)row * NTRAIN;
        int taken = 0;
        for (int i = 0; i < NTRAIN && taken < kneed; ++i) {
            if (fmap(s[i]) == T_lo) { cls[labels[i]]++; taken++; }
        }
    }
    __syncthreads();

    if (tid < NCLS) atomicAdd(&g_counts[b * NCLS + tid], cls[tid]);
}

// ---------------- kernel 4: conformal p-values, argmax, creds ----------------
__global__ void final_kernel(const int* __restrict__ cali, float* __restrict__ out) {
    __shared__ int cal[NCALI];
    for (int i = threadIdx.x; i < NCALI; i += blockDim.x) cal[i] = cali[i];
    __syncthreads();
    int b = threadIdx.x;
    if (b >= BATCH) return;
    float best = -1.f;
    int arg = 0;
    float pv[NCLS];
#pragma unroll
    for (int c = 0; c < NCLS; ++c) {
        int nc = LAYERS * KNN - g_counts[b * NCLS + c];
        int lo = 0, hi = NCALI;
        while (lo < hi) {
            int mid = (lo + hi) >> 1;
            if (cal[mid] < nc) lo = mid + 1; else hi = mid;
        }
        float p = (float)(NCALI - lo) / (float)NCALI;
        pv[c] = p;
        if (p > best) { best = p; arg = c; }
    }
#pragma unroll
    for (int c = 0; c < NCLS; ++c)
        out[b * NCLS + c] = (c == arg) ? pv[c] : 0.0f;
}

// ---------------- launch ----------------
extern "C" void kernel_launch(void* const* d_in, const int* in_sizes, int n_in,
                              void* d_out, int out_size) {
    const float* train = (const float*)d_in[0];
    const float* query = (const float*)d_in[1];
    const int* labels = (const int*)d_in[2];
    const int* cali = (const int*)d_in[3];
    float* out = (float*)d_out;

    norm_kernel<<<(LAYERS * NTRAIN + 7) / 8, 256>>>(train);

    dim3 ggrid((NTRAIN + GBN - 1) / GBN, BATCH / GBM, LAYERS);
    gemm_kernel<<<ggrid, 256>>>(query, train);

    topk_kernel<<<LAYERS * BATCH, 256>>>(labels);

    final_kernel<<<1, 256>>>(cali, out);
}